// round 7
// baseline (speedup 1.0000x reference)
#include <cuda_runtime.h>
#include <cstdint>

// ---------------------------------------------------------------------------
// Problem constants
// ---------------------------------------------------------------------------
#define NN    512
#define TT    64
#define DIN   1024
#define DOUT  1024
#define MTOT  (NN * TT)          // 32768

// GEMM tiling: CTA 128x128, 256 threads, 8x8/thread, KC=32, 3-stage cp.async.
#define KC      32
#define KTILES  (DIN / KC)       // 32
#define NSTAGE  3
#define STAGE_FLOATS (KC * 128 * 2)        // A + B = 8192 floats = 32768 B
#define STAGE_BYTES  (STAGE_FLOATS * 4)    // 32768
#define STG_PITCH   129                    // epilogue staging [o:128][129][m:128]
#define SMEM_BYTES  (NSTAGE * STAGE_BYTES) // 98304 >= 128*129*4 = 66048

// ---------------------------------------------------------------------------
// Device scratch (sanctioned: __device__ globals)
// ---------------------------------------------------------------------------
__device__ float g_at[(size_t)DIN * MTOT];  // 128 MB: A transposed [k][m]
__device__ float g_wt[DIN * DOUT];          // 4 MB: BN-folded W transposed [k][o]
__device__ float g_bstep[DOUT];

// ---------------------------------------------------------------------------
// Inline PTX
// ---------------------------------------------------------------------------
__device__ __forceinline__ uint32_t smem_to_u32(const void* p) {
    uint32_t a;
    asm("{ .reg .u64 t; cvta.to.shared.u64 t, %1; cvt.u32.u64 %0, t; }"
        : "=r"(a) : "l"(p));
    return a;
}

__device__ __forceinline__ void cpasync16(uint32_t s, const void* g) {
    asm volatile("cp.async.cg.shared.global [%0], [%1], 16;"
                 :: "r"(s), "l"(g) : "memory");
}

// ---------------------------------------------------------------------------
// Prep A: transpose A[m][k] -> At[k][m].  32x32 tiles, 32x8 threads.
// ---------------------------------------------------------------------------
__global__ __launch_bounds__(256)
void transpose_a_kernel(const float* __restrict__ A) {
    __shared__ float s[32][33];
    const int k0 = blockIdx.x * 32;          // 32 k-tiles
    const int m0 = blockIdx.y * 32;          // 1024 m-tiles
    const int tx = threadIdx.x, ty = threadIdx.y;
#pragma unroll
    for (int i = 0; i < 4; i++) {
        const int m = ty + i * 8;
        s[m][tx] = A[(size_t)(m0 + m) * DIN + k0 + tx];
    }
    __syncthreads();
#pragma unroll
    for (int i = 0; i < 4; i++) {
        const int k = ty + i * 8;
        g_at[(size_t)(k0 + k) * MTOT + m0 + tx] = s[tx][k];
    }
}

// ---------------------------------------------------------------------------
// Prep W: fold BN (ratio = gamma/sqrt(var), no eps — same arithmetic as R1)
// and transpose -> Wt[k][o]. Also compute b_step. 32x32 tiles.
// ---------------------------------------------------------------------------
__global__ __launch_bounds__(256)
void prep_w_kernel(const float* __restrict__ w,
                   const float* __restrict__ bias,
                   const float* __restrict__ gamma,
                   const float* __restrict__ beta,
                   const float* __restrict__ mean,
                   const float* __restrict__ var) {
    __shared__ float s[32][33];
    __shared__ float rat[32];
    const int k0 = blockIdx.x * 32;          // 32 k-tiles
    const int o0 = blockIdx.y * 32;          // 32 o-tiles
    const int tx = threadIdx.x, ty = threadIdx.y;
    if (ty == 0) {
        const int o = o0 + tx;
        const float ratio = gamma[o] / sqrtf(var[o]);
        rat[tx] = ratio;
        if (blockIdx.x == 0) {
            g_bstep[o] = ((bias[o] - mean[o]) * ratio + beta[o]) * (1.0f / (float)TT);
        }
    }
    __syncthreads();
#pragma unroll
    for (int i = 0; i < 4; i++) {
        const int oc = ty + i * 8;
        s[oc][tx] = w[(size_t)(o0 + oc) * DIN + k0 + tx] * rat[oc];
    }
    __syncthreads();
#pragma unroll
    for (int i = 0; i < 4; i++) {
        const int k = ty + i * 8;
        g_wt[(size_t)(k0 + k) * DOUT + o0 + tx] = s[tx][k];
    }
}

// ---------------------------------------------------------------------------
// Stage loader: cp.async straight into [k][row] layout.
// A stage: KC x 128 floats at stage base; B stage: +16384 bytes.
// chunk c in [0,1024): k = c>>5, cg = c&31  -> 16B at k*512 + cg*16.
// ---------------------------------------------------------------------------
__device__ __forceinline__ void load_stage(uint32_t sbu, int stage, int kt,
                                           int m0, int o0, int tid) {
    const uint32_t st = sbu + stage * STAGE_BYTES;
    const int k0 = kt * KC;
    const float* gA = g_at + (size_t)k0 * MTOT + m0;
    const float* gB = g_wt + (size_t)k0 * DOUT + o0;
#pragma unroll
    for (int i = 0; i < 4; i++) {
        const int c = tid + i * 256;
        const int k = c >> 5, cg = c & 31;
        cpasync16(st + k * 512 + cg * 16, gA + (size_t)k * MTOT + cg * 4);
        cpasync16(st + 16384 + k * 512 + cg * 16, gB + (size_t)k * DOUT + cg * 4);
    }
    asm volatile("cp.async.commit_group;" ::: "memory");
}

// ---------------------------------------------------------------------------
// Fused SGEMM + IF scan. fma chain: acc=0, k ascending, one fmaf per k
// (bit-identical to R1/R5/R6 -> rel_err 8.103138e-4 guaranteed).
// Warp layout as R1: 4x2 warps, rbase +0/+16, cbase +0/+32 (conflict-free).
// Inner loop: kb(4, not unrolled) x j(8, unrolled) -> ~9KB body, I$-resident;
// fragment double-buffer parity (j&1) is compile-time -> frags stay in regs.
// ---------------------------------------------------------------------------
__global__ __launch_bounds__(256, 2)
void gemm_if_kernel(float* __restrict__ spike_out,
                    float* __restrict__ count_out) {
    extern __shared__ __align__(16) float smem[];
    const uint32_t sbu = smem_to_u32(smem);

    const int tid  = threadIdx.x;
    const int warp = tid >> 5;
    const int lane = tid & 31;
    const int wr   = warp >> 1;
    const int wc   = warp & 1;
    const int rbase = wr * 32 + ((lane >> 3) << 2);
    const int cbase = wc * 64 + ((lane & 7) << 2);

    const int o0 = blockIdx.x * 128;        // 8 o-tiles (fast dim: A L2-shared)
    const int m0 = blockIdx.y * 128;        // 256 m-tiles

    float acc[8][8];
#pragma unroll
    for (int i = 0; i < 8; i++)
#pragma unroll
        for (int j = 0; j < 8; j++) acc[i][j] = 0.0f;

    // Prologue: issue NSTAGE-1 stages
    load_stage(sbu, 0, 0, m0, o0, tid);
    load_stage(sbu, 1, 1, m0, o0, tid);

    int stage = 0;
    for (int kt = 0; kt < KTILES; kt++) {
        asm volatile("cp.async.wait_group 1;" ::: "memory");
        __syncthreads();

        if (kt + 2 < KTILES) {
            int ns = stage + 2; if (ns >= NSTAGE) ns -= NSTAGE;
            load_stage(sbu, ns, kt + 2, m0, o0, tid);
        }

        const float* As = smem + stage * STAGE_FLOATS;
        const float* Bs = As + KC * 128;

        float af[2][8], bf[2][8];
        *(float4*)&af[0][0] = *(const float4*)&As[rbase];
        *(float4*)&af[0][4] = *(const float4*)&As[rbase + 16];
        *(float4*)&bf[0][0] = *(const float4*)&Bs[cbase];
        *(float4*)&bf[0][4] = *(const float4*)&Bs[cbase + 32];

#pragma unroll 1
        for (int kb = 0; kb < 4; kb++) {
#pragma unroll
            for (int j = 0; j < 8; j++) {
                const int k = kb * 8 + j;
                const int cur = j & 1, nxt = cur ^ 1;
                if (k < KC - 1) {
                    *(float4*)&af[nxt][0] = *(const float4*)&As[(k + 1) * 128 + rbase];
                    *(float4*)&af[nxt][4] = *(const float4*)&As[(k + 1) * 128 + rbase + 16];
                    *(float4*)&bf[nxt][0] = *(const float4*)&Bs[(k + 1) * 128 + cbase];
                    *(float4*)&bf[nxt][4] = *(const float4*)&Bs[(k + 1) * 128 + cbase + 32];
                }
#pragma unroll
                for (int i = 0; i < 8; i++)
#pragma unroll
                    for (int jj = 0; jj < 8; jj++)
                        acc[i][jj] = fmaf(af[cur][i], bf[cur][jj], acc[i][jj]);
            }
        }

        stage = stage + 1; if (stage >= NSTAGE) stage -= NSTAGE;
    }
    __syncthreads();   // all compute done before reusing smem for staging

    // ---- Epilogue: stage [o_local][m_local] (pitch 129), fused IF scan ----
    float* stg = smem;
#pragma unroll
    for (int i = 0; i < 8; i++) {
        const int ml = rbase + (i & 3) + ((i >> 2) << 4);
#pragma unroll
        for (int j = 0; j < 8; j++) {
            const int ol = cbase + (j & 3) + ((j >> 2) << 5);
            stg[ol * STG_PITCH + ml] = acc[i][j];
        }
    }
    __syncthreads();

    // 256 tasks: o_l in [0,128) x n-group {0,1}; m_l = nl*64 + t
    const int ol = tid & 127;
    const int nl = tid >> 7;
    const int n  = (m0 >> 6) + nl;
    const int og = o0 + ol;
    const float bs = g_bstep[og];
    const float* col = stg + ol * STG_PITCH + nl * 64;
    float* so = spike_out + (size_t)n * TT * DOUT + og;

    float pot = 0.0f, cnt = 0.0f;
#pragma unroll 8
    for (int t = 0; t < TT; t++) {
        pot = (pot + col[t]) + bs;          // left-assoc, identical to R1 scan
        const float spk = (pot >= 1.0f) ? 1.0f : 0.0f;
        so[(size_t)t * DOUT] = spk;
        pot -= spk;
        cnt += spk;
    }
    count_out[(size_t)n * DOUT + og] = cnt;
}

// ---------------------------------------------------------------------------
// Launch
// ---------------------------------------------------------------------------
extern "C" void kernel_launch(void* const* d_in, const int* in_sizes, int n_in,
                              void* d_out, int out_size) {
    (void)in_sizes; (void)n_in; (void)out_size;

    const float* x_st  = (const float*)d_in[0];  // (512, 64, 1024) binary
    const float* w     = (const float*)d_in[2];
    const float* bias  = (const float*)d_in[3];
    const float* gamma = (const float*)d_in[4];
    const float* beta  = (const float*)d_in[5];
    const float* mean  = (const float*)d_in[6];
    const float* var   = (const float*)d_in[7];

    float* out       = (float*)d_out;
    float* spike_out = out;                                 // 512*64*1024
    float* count_out = out + (size_t)MTOT * DOUT;           // 512*1024

    {
        dim3 blk(32, 8);
        dim3 grd(DIN / 32, MTOT / 32);                      // (32, 1024)
        transpose_a_kernel<<<grd, blk>>>(x_st);
        dim3 grd2(DIN / 32, DOUT / 32);                     // (32, 32)
        prep_w_kernel<<<grd2, blk>>>(w, bias, gamma, beta, mean, var);
    }

    cudaFuncSetAttribute(gemm_if_kernel,
                         cudaFuncAttributeMaxDynamicSharedMemorySize, SMEM_BYTES);

    dim3 grid(DOUT / 128, MTOT / 128);                      // (8, 256)
    gemm_if_kernel<<<grid, 256, SMEM_BYTES>>>(spike_out, count_out);
}

// round 8
// speedup vs baseline: 1.1374x; 1.1374x over previous
#include <cuda_runtime.h>
#include <cstdint>

// ---------------------------------------------------------------------------
// Problem constants
// ---------------------------------------------------------------------------
#define NN    512
#define TT    64
#define DIN   1024
#define DOUT  1024
#define MTOT  (NN * TT)          // 32768

// GEMM tiling (R6 structure): CTA 128x128, 256 threads, 8x8/thread, KC=16,
// 4-stage cp.async pipeline. Inner math: packed fma.rn.f32x2.
#define KC      16
#define KTILES  (DIN / KC)       // 64
#define NSTAGE  4
#define STAGE_BYTES (KC * 128 * 4 * 2)     // A(8KB) + B(8KB) = 16384
#define STG_PITCH   129                    // epilogue staging [o:128][129][m:128]
#define SMEM_BYTES  66048                  // max(4*16384=65536, 128*129*4=66048)

// ---------------------------------------------------------------------------
// Device scratch (sanctioned: __device__ globals)
// ---------------------------------------------------------------------------
__device__ float g_at[(size_t)DIN * MTOT];  // 128 MB: A transposed [k][m]
__device__ float g_wt[DIN * DOUT];          // 4 MB: BN-folded W transposed [k][o]
__device__ float g_bstep[DOUT];

// ---------------------------------------------------------------------------
// Inline PTX
// ---------------------------------------------------------------------------
__device__ __forceinline__ uint32_t smem_to_u32(const void* p) {
    uint32_t a;
    asm("{ .reg .u64 t; cvta.to.shared.u64 t, %1; cvt.u32.u64 %0, t; }"
        : "=r"(a) : "l"(p));
    return a;
}

__device__ __forceinline__ void cpasync16(uint32_t s, const void* g) {
    asm volatile("cp.async.cg.shared.global [%0], [%1], 16;"
                 :: "r"(s), "l"(g) : "memory");
}

// Packed dual fp32 FMA: d.lo = fma.rn(a.lo,b.lo,d.lo), d.hi likewise.
// Bit-identical per half to scalar fma.rn.f32 -> chain preserved.
__device__ __forceinline__ void ffma2(unsigned long long& d,
                                      unsigned long long a,
                                      unsigned long long b) {
    asm("fma.rn.f32x2 %0, %1, %2, %0;" : "+l"(d) : "l"(a), "l"(b));
}

__device__ __forceinline__ unsigned long long pack2(float x) {
    unsigned long long r;
    asm("mov.b64 %0, {%1, %1};" : "=l"(r) : "f"(x));
    return r;
}

__device__ __forceinline__ void unpack2(unsigned long long v, float& lo, float& hi) {
    asm("mov.b64 {%0, %1}, %2;" : "=f"(lo), "=f"(hi) : "l"(v));
}

// ---------------------------------------------------------------------------
// Prep A: transpose A[m][k] -> At[k][m].  32x32 tiles, 32x8 threads.
// ---------------------------------------------------------------------------
__global__ __launch_bounds__(256)
void transpose_a_kernel(const float* __restrict__ A) {
    __shared__ float s[32][33];
    const int k0 = blockIdx.x * 32;
    const int m0 = blockIdx.y * 32;
    const int tx = threadIdx.x, ty = threadIdx.y;
#pragma unroll
    for (int i = 0; i < 4; i++) {
        const int m = ty + i * 8;
        s[m][tx] = A[(size_t)(m0 + m) * DIN + k0 + tx];
    }
    __syncthreads();
#pragma unroll
    for (int i = 0; i < 4; i++) {
        const int k = ty + i * 8;
        g_at[(size_t)(k0 + k) * MTOT + m0 + tx] = s[tx][k];
    }
}

// ---------------------------------------------------------------------------
// Prep W: fold BN (ratio = gamma/sqrt(var), no eps — same arithmetic as R1)
// and transpose -> Wt[k][o]. Also compute b_step.
// ---------------------------------------------------------------------------
__global__ __launch_bounds__(256)
void prep_w_kernel(const float* __restrict__ w,
                   const float* __restrict__ bias,
                   const float* __restrict__ gamma,
                   const float* __restrict__ beta,
                   const float* __restrict__ mean,
                   const float* __restrict__ var) {
    __shared__ float s[32][33];
    __shared__ float rat[32];
    const int k0 = blockIdx.x * 32;
    const int o0 = blockIdx.y * 32;
    const int tx = threadIdx.x, ty = threadIdx.y;
    if (ty == 0) {
        const int o = o0 + tx;
        const float ratio = gamma[o] / sqrtf(var[o]);
        rat[tx] = ratio;
        if (blockIdx.x == 0) {
            g_bstep[o] = ((bias[o] - mean[o]) * ratio + beta[o]) * (1.0f / (float)TT);
        }
    }
    __syncthreads();
#pragma unroll
    for (int i = 0; i < 4; i++) {
        const int oc = ty + i * 8;
        s[oc][tx] = w[(size_t)(o0 + oc) * DIN + k0 + tx] * rat[oc];
    }
    __syncthreads();
#pragma unroll
    for (int i = 0; i < 4; i++) {
        const int k = ty + i * 8;
        g_wt[(size_t)(k0 + k) * DOUT + o0 + tx] = s[tx][k];
    }
}

// ---------------------------------------------------------------------------
// Stage loader (R6): cp.async straight into [k][row] layout.
// ---------------------------------------------------------------------------
__device__ __forceinline__ void load_stage(uint32_t sbu, int stage, int kt,
                                           int m0, int o0, int tid) {
    const uint32_t st = sbu + stage * STAGE_BYTES;
    const int k0 = kt * KC;
    const float* gA = g_at + (size_t)k0 * MTOT + m0;
    const float* gB = g_wt + (size_t)k0 * DOUT + o0;
#pragma unroll
    for (int i = 0; i < 2; i++) {
        const int c = tid + i * 256;
        const int k = c >> 5, cg = c & 31;
        cpasync16(st + k * 512 + cg * 16, gA + (size_t)k * MTOT + cg * 4);
        cpasync16(st + 8192 + k * 512 + cg * 16, gB + (size_t)k * DOUT + cg * 4);
    }
    asm volatile("cp.async.commit_group;" ::: "memory");
}

// ---------------------------------------------------------------------------
// Fused SGEMM + IF scan, packed-FFMA2 micro-kernel.
// Chain: acc=0, k ascending, one fma.rn per k per output -> outputs
// bit-identical to R1/R5/R6 (rel_err 8.103138e-4).
// ---------------------------------------------------------------------------
__global__ __launch_bounds__(256, 2)
void gemm_if_kernel(float* __restrict__ spike_out,
                    float* __restrict__ count_out) {
    extern __shared__ __align__(16) float smem[];
    const uint32_t sbu = smem_to_u32(smem);

    const int tid  = threadIdx.x;
    const int warp = tid >> 5;
    const int lane = tid & 31;
    const int wr   = warp >> 1;
    const int wc   = warp & 1;
    const int rbase = wr * 32 + ((lane >> 3) << 2);
    const int cbase = wc * 64 + ((lane & 7) << 2);

    const int o0 = blockIdx.x * 128;        // 8 o-tiles (A tiles L2-shared)
    const int m0 = blockIdx.y * 128;        // 256 m-tiles

    // acc2[i][p]: packed pair (j=2p, j=2p+1); p 0..1 -> cbase+0..3, p 2..3 -> cbase+32..35
    unsigned long long acc2[8][4];
#pragma unroll
    for (int i = 0; i < 8; i++)
#pragma unroll
        for (int p = 0; p < 4; p++) acc2[i][p] = 0ull;

    load_stage(sbu, 0, 0, m0, o0, tid);
    load_stage(sbu, 1, 1, m0, o0, tid);
    load_stage(sbu, 2, 2, m0, o0, tid);

    for (int kt = 0; kt < KTILES; kt++) {
        asm volatile("cp.async.wait_group 2;" ::: "memory");
        __syncthreads();

        if (kt + 3 < KTILES)
            load_stage(sbu, (kt + 3) & 3, kt + 3, m0, o0, tid);

        const float* As = smem + (kt & 3) * (STAGE_BYTES / 4);
        const float* Bs = As + 2048;

#pragma unroll
        for (int k = 0; k < KC; k++) {
            float a[8];
            *(float4*)&a[0] = *(const float4*)&As[k * 128 + rbase];
            *(float4*)&a[4] = *(const float4*)&As[k * 128 + rbase + 16];
            const ulonglong2 bv0 = *(const ulonglong2*)&Bs[k * 128 + cbase];
            const ulonglong2 bv1 = *(const ulonglong2*)&Bs[k * 128 + cbase + 32];
#pragma unroll
            for (int i = 0; i < 8; i++) {
                const unsigned long long a2 = pack2(a[i]);
                ffma2(acc2[i][0], a2, bv0.x);
                ffma2(acc2[i][1], a2, bv0.y);
                ffma2(acc2[i][2], a2, bv1.x);
                ffma2(acc2[i][3], a2, bv1.y);
            }
        }
    }
    __syncthreads();   // all compute done before reusing smem for staging

    // ---- Epilogue: unpack, stage [o_local][m_local] (pitch 129), IF scan ----
    float* stg = smem;
#pragma unroll
    for (int i = 0; i < 8; i++) {
        const int ml = rbase + (i & 3) + ((i >> 2) << 4);
#pragma unroll
        for (int p = 0; p < 4; p++) {
            float lo, hi;
            unpack2(acc2[i][p], lo, hi);
            const int ol = cbase + ((2 * p) & 3) + ((p >> 1) << 5);
            stg[ol * STG_PITCH + ml]       = lo;
            stg[(ol + 1) * STG_PITCH + ml] = hi;
        }
    }
    __syncthreads();

    // 256 tasks: o_l in [0,128) x n-group {0,1}; m_l = nl*64 + t
    const int ol = tid & 127;
    const int nl = tid >> 7;
    const int n  = (m0 >> 6) + nl;
    const int og = o0 + ol;
    const float bs = g_bstep[og];
    const float* col = stg + ol * STG_PITCH + nl * 64;
    float* so = spike_out + (size_t)n * TT * DOUT + og;

    float pot = 0.0f, cnt = 0.0f;
#pragma unroll 8
    for (int t = 0; t < TT; t++) {
        pot = (pot + col[t]) + bs;          // left-assoc, identical to R1 scan
        const float spk = (pot >= 1.0f) ? 1.0f : 0.0f;
        so[(size_t)t * DOUT] = spk;
        pot -= spk;
        cnt += spk;
    }
    count_out[(size_t)n * DOUT + og] = cnt;
}

// ---------------------------------------------------------------------------
// Launch
// ---------------------------------------------------------------------------
extern "C" void kernel_launch(void* const* d_in, const int* in_sizes, int n_in,
                              void* d_out, int out_size) {
    (void)in_sizes; (void)n_in; (void)out_size;

    const float* x_st  = (const float*)d_in[0];  // (512, 64, 1024) binary
    const float* w     = (const float*)d_in[2];
    const float* bias  = (const float*)d_in[3];
    const float* gamma = (const float*)d_in[4];
    const float* beta  = (const float*)d_in[5];
    const float* mean  = (const float*)d_in[6];
    const float* var   = (const float*)d_in[7];

    float* out       = (float*)d_out;
    float* spike_out = out;                                 // 512*64*1024
    float* count_out = out + (size_t)MTOT * DOUT;           // 512*1024

    {
        dim3 blk(32, 8);
        dim3 grd(DIN / 32, MTOT / 32);                      // (32, 1024)
        transpose_a_kernel<<<grd, blk>>>(x_st);
        dim3 grd2(DIN / 32, DOUT / 32);                     // (32, 32)
        prep_w_kernel<<<grd2, blk>>>(w, bias, gamma, beta, mean, var);
    }

    cudaFuncSetAttribute(gemm_if_kernel,
                         cudaFuncAttributeMaxDynamicSharedMemorySize, SMEM_BYTES);

    dim3 grid(DOUT / 128, MTOT / 128);                      // (8, 256)
    gemm_if_kernel<<<grid, 256, SMEM_BYTES>>>(spike_out, count_out);
}

// round 9
// speedup vs baseline: 1.2212x; 1.0736x over previous
#include <cuda_runtime.h>
#include <cstdint>

// ---------------------------------------------------------------------------
// Problem constants
// ---------------------------------------------------------------------------
#define NN    512
#define TT    64
#define DIN   1024
#define DOUT  1024
#define MTOT  (NN * TT)          // 32768

// GEMM tiling: CTA 128x128, 256 threads, 8x8/thread, KC=32 fully unrolled,
// 3-stage cp.async pipeline. Inner math: packed fma.rn.f32x2 (R8 body).
#define KC      32
#define KTILES  (DIN / KC)       // 32
#define NSTAGE  3
#define STAGE_BYTES (KC * 128 * 4 * 2)     // A(16KB) + B(16KB) = 32768
#define STAGE_FLOATS (STAGE_BYTES / 4)
#define STG_PITCH   129                    // epilogue staging [o:128][129][m:128]
#define SMEM_BYTES  (NSTAGE * STAGE_BYTES) // 98304 >= 128*129*4 = 66048

// ---------------------------------------------------------------------------
// Device scratch (sanctioned: __device__ globals)
// ---------------------------------------------------------------------------
__device__ float g_at[(size_t)DIN * MTOT];  // 128 MB: A transposed [k][m]
__device__ float g_wt[DIN * DOUT];          // 4 MB: BN-folded W transposed [k][o]
__device__ float g_bstep[DOUT];

// ---------------------------------------------------------------------------
// Inline PTX
// ---------------------------------------------------------------------------
__device__ __forceinline__ uint32_t smem_to_u32(const void* p) {
    uint32_t a;
    asm("{ .reg .u64 t; cvta.to.shared.u64 t, %1; cvt.u32.u64 %0, t; }"
        : "=r"(a) : "l"(p));
    return a;
}

__device__ __forceinline__ void cpasync16(uint32_t s, const void* g) {
    asm volatile("cp.async.cg.shared.global [%0], [%1], 16;"
                 :: "r"(s), "l"(g) : "memory");
}

// Packed dual fp32 FMA: per-half bit-identical to scalar fma.rn.f32.
__device__ __forceinline__ void ffma2(unsigned long long& d,
                                      unsigned long long a,
                                      unsigned long long b) {
    asm("fma.rn.f32x2 %0, %1, %2, %0;" : "+l"(d) : "l"(a), "l"(b));
}

__device__ __forceinline__ unsigned long long pack2(float x) {
    unsigned long long r;
    asm("mov.b64 %0, {%1, %1};" : "=l"(r) : "f"(x));
    return r;
}

__device__ __forceinline__ void unpack2(unsigned long long v, float& lo, float& hi) {
    asm("mov.b64 {%0, %1}, %2;" : "=f"(lo), "=f"(hi) : "l"(v));
}

// ---------------------------------------------------------------------------
// Prep A: transpose A[m][k] -> At[k][m].  32x32 tiles, 32x8 threads.
// ---------------------------------------------------------------------------
__global__ __launch_bounds__(256)
void transpose_a_kernel(const float* __restrict__ A) {
    __shared__ float s[32][33];
    const int k0 = blockIdx.x * 32;
    const int m0 = blockIdx.y * 32;
    const int tx = threadIdx.x, ty = threadIdx.y;
#pragma unroll
    for (int i = 0; i < 4; i++) {
        const int m = ty + i * 8;
        s[m][tx] = A[(size_t)(m0 + m) * DIN + k0 + tx];
    }
    __syncthreads();
#pragma unroll
    for (int i = 0; i < 4; i++) {
        const int k = ty + i * 8;
        g_at[(size_t)(k0 + k) * MTOT + m0 + tx] = s[tx][k];
    }
}

// ---------------------------------------------------------------------------
// Prep W: fold BN (ratio = gamma/sqrt(var), no eps — same arithmetic as R1)
// and transpose -> Wt[k][o]. Also compute b_step.
// ---------------------------------------------------------------------------
__global__ __launch_bounds__(256)
void prep_w_kernel(const float* __restrict__ w,
                   const float* __restrict__ bias,
                   const float* __restrict__ gamma,
                   const float* __restrict__ beta,
                   const float* __restrict__ mean,
                   const float* __restrict__ var) {
    __shared__ float s[32][33];
    __shared__ float rat[32];
    const int k0 = blockIdx.x * 32;
    const int o0 = blockIdx.y * 32;
    const int tx = threadIdx.x, ty = threadIdx.y;
    if (ty == 0) {
        const int o = o0 + tx;
        const float ratio = gamma[o] / sqrtf(var[o]);
        rat[tx] = ratio;
        if (blockIdx.x == 0) {
            g_bstep[o] = ((bias[o] - mean[o]) * ratio + beta[o]) * (1.0f / (float)TT);
        }
    }
    __syncthreads();
#pragma unroll
    for (int i = 0; i < 4; i++) {
        const int oc = ty + i * 8;
        s[oc][tx] = w[(size_t)(o0 + oc) * DIN + k0 + tx] * rat[oc];
    }
    __syncthreads();
#pragma unroll
    for (int i = 0; i < 4; i++) {
        const int k = ty + i * 8;
        g_wt[(size_t)(k0 + k) * DOUT + o0 + tx] = s[tx][k];
    }
}

// ---------------------------------------------------------------------------
// Stage loader: cp.async straight into [k][row] layout.
// A stage: KC x 128 floats at base; B stage: +16384 bytes.
// chunk c in [0,1024) per matrix: k = c>>5, cg = c&31 -> 16B at k*512 + cg*16.
// ---------------------------------------------------------------------------
__device__ __forceinline__ void load_stage(uint32_t sbu, int stage, int kt,
                                           int m0, int o0, int tid) {
    const uint32_t st = sbu + stage * STAGE_BYTES;
    const int k0 = kt * KC;
    const float* gA = g_at + (size_t)k0 * MTOT + m0;
    const float* gB = g_wt + (size_t)k0 * DOUT + o0;
#pragma unroll
    for (int i = 0; i < 4; i++) {
        const int c = tid + i * 256;
        const int k = c >> 5, cg = c & 31;
        cpasync16(st + k * 512 + cg * 16, gA + (size_t)k * MTOT + cg * 4);
        cpasync16(st + 16384 + k * 512 + cg * 16, gB + (size_t)k * DOUT + cg * 4);
    }
    asm volatile("cp.async.commit_group;" ::: "memory");
}

// ---------------------------------------------------------------------------
// Fused SGEMM + IF scan, packed-FFMA2 micro-kernel (R8 body), KC=32 fully
// unrolled, 3-stage pipeline. Chain: acc=0, k ascending, one fma.rn per k
// -> outputs bit-identical to R1/R5/R6/R8 (rel_err 8.103138e-4).
// ---------------------------------------------------------------------------
__global__ __launch_bounds__(256, 2)
void gemm_if_kernel(float* __restrict__ spike_out,
                    float* __restrict__ count_out) {
    extern __shared__ __align__(16) float smem[];
    const uint32_t sbu = smem_to_u32(smem);

    const int tid  = threadIdx.x;
    const int warp = tid >> 5;
    const int lane = tid & 31;
    const int wr   = warp >> 1;
    const int wc   = warp & 1;
    const int rbase = wr * 32 + ((lane >> 3) << 2);
    const int cbase = wc * 64 + ((lane & 7) << 2);

    const int o0 = blockIdx.x * 128;        // 8 o-tiles (A tiles L2-shared)
    const int m0 = blockIdx.y * 128;        // 256 m-tiles

    unsigned long long acc2[8][4];
#pragma unroll
    for (int i = 0; i < 8; i++)
#pragma unroll
        for (int p = 0; p < 4; p++) acc2[i][p] = 0ull;

    load_stage(sbu, 0, 0, m0, o0, tid);
    load_stage(sbu, 1, 1, m0, o0, tid);

    int stage = 0;
    for (int kt = 0; kt < KTILES; kt++) {
        asm volatile("cp.async.wait_group 1;" ::: "memory");
        __syncthreads();

        if (kt + 2 < KTILES) {
            int ns = stage + 2; if (ns >= NSTAGE) ns -= NSTAGE;
            load_stage(sbu, ns, kt + 2, m0, o0, tid);
        }

        const float* As = smem + stage * STAGE_FLOATS;
        const float* Bs = As + KC * 128;

#pragma unroll
        for (int k = 0; k < KC; k++) {
            float a[8];
            *(float4*)&a[0] = *(const float4*)&As[k * 128 + rbase];
            *(float4*)&a[4] = *(const float4*)&As[k * 128 + rbase + 16];
            const ulonglong2 bv0 = *(const ulonglong2*)&Bs[k * 128 + cbase];
            const ulonglong2 bv1 = *(const ulonglong2*)&Bs[k * 128 + cbase + 32];
#pragma unroll
            for (int i = 0; i < 8; i++) {
                const unsigned long long a2 = pack2(a[i]);
                ffma2(acc2[i][0], a2, bv0.x);
                ffma2(acc2[i][1], a2, bv0.y);
                ffma2(acc2[i][2], a2, bv1.x);
                ffma2(acc2[i][3], a2, bv1.y);
            }
        }

        stage = stage + 1; if (stage >= NSTAGE) stage -= NSTAGE;
    }
    __syncthreads();   // all compute done before reusing smem for staging

    // ---- Epilogue: unpack, stage [o_local][m_local] (pitch 129), IF scan ----
    float* stg = smem;
#pragma unroll
    for (int i = 0; i < 8; i++) {
        const int ml = rbase + (i & 3) + ((i >> 2) << 4);
#pragma unroll
        for (int p = 0; p < 4; p++) {
            float lo, hi;
            unpack2(acc2[i][p], lo, hi);
            const int ol = cbase + ((2 * p) & 3) + ((p >> 1) << 5);
            stg[ol * STG_PITCH + ml]       = lo;
            stg[(ol + 1) * STG_PITCH + ml] = hi;
        }
    }
    __syncthreads();

    // 256 tasks: o_l in [0,128) x n-group {0,1}; m_l = nl*64 + t
    const int ol = tid & 127;
    const int nl = tid >> 7;
    const int n  = (m0 >> 6) + nl;
    const int og = o0 + ol;
    const float bs = g_bstep[og];
    const float* col = stg + ol * STG_PITCH + nl * 64;
    float* so = spike_out + (size_t)n * TT * DOUT + og;

    float pot = 0.0f, cnt = 0.0f;
#pragma unroll 8
    for (int t = 0; t < TT; t++) {
        pot = (pot + col[t]) + bs;          // left-assoc, identical to R1 scan
        const float spk = (pot >= 1.0f) ? 1.0f : 0.0f;
        so[(size_t)t * DOUT] = spk;
        pot -= spk;
        cnt += spk;
    }
    count_out[(size_t)n * DOUT + og] = cnt;
}

// ---------------------------------------------------------------------------
// Launch
// ---------------------------------------------------------------------------
extern "C" void kernel_launch(void* const* d_in, const int* in_sizes, int n_in,
                              void* d_out, int out_size) {
    (void)in_sizes; (void)n_in; (void)out_size;

    const float* x_st  = (const float*)d_in[0];  // (512, 64, 1024) binary
    const float* w     = (const float*)d_in[2];
    const float* bias  = (const float*)d_in[3];
    const float* gamma = (const float*)d_in[4];
    const float* beta  = (const float*)d_in[5];
    const float* mean  = (const float*)d_in[6];
    const float* var   = (const float*)d_in[7];

    float* out       = (float*)d_out;
    float* spike_out = out;                                 // 512*64*1024
    float* count_out = out + (size_t)MTOT * DOUT;           // 512*1024

    {
        dim3 blk(32, 8);
        dim3 grd(DIN / 32, MTOT / 32);                      // (32, 1024)
        transpose_a_kernel<<<grd, blk>>>(x_st);
        dim3 grd2(DIN / 32, DOUT / 32);                     // (32, 32)
        prep_w_kernel<<<grd2, blk>>>(w, bias, gamma, beta, mean, var);
    }

    cudaFuncSetAttribute(gemm_if_kernel,
                         cudaFuncAttributeMaxDynamicSharedMemorySize, SMEM_BYTES);

    dim3 grid(DOUT / 128, MTOT / 128);                      // (8, 256)
    gemm_if_kernel<<<grid, 256, SMEM_BYTES>>>(spike_out, count_out);
}

// round 10
// speedup vs baseline: 1.2254x; 1.0034x over previous
#include <cuda_runtime.h>
#include <cstdint>

// ---------------------------------------------------------------------------
// Problem constants
// ---------------------------------------------------------------------------
#define NN    512
#define TT    64
#define DIN   1024
#define DOUT  1024
#define MTOT  (NN * TT)          // 32768

// GEMM tiling: CTA 128x128, 256 threads, 8x8/thread, KC=32 fully unrolled,
// 3-stage cp.async pipeline, packed fma.rn.f32x2 micro-kernel.
#define KC      32
#define KTILES  (DIN / KC)       // 32
#define NSTAGE  3
#define STAGE_BYTES (KC * 128 * 4 * 2)     // A(16KB) + B(16KB) = 32768
#define STAGE_FLOATS (STAGE_BYTES / 4)
#define STG_PITCH   129                    // epilogue staging [o:128][129][m:128]
#define SMEM_BYTES  (NSTAGE * STAGE_BYTES) // 98304 >= 128*129*4 = 66048

// ---------------------------------------------------------------------------
// Device scratch (sanctioned: __device__ globals)
// ---------------------------------------------------------------------------
__device__ float g_at[(size_t)DIN * MTOT];  // 128 MB: A transposed [k][m]
__device__ float g_wt[DIN * DOUT];          // 4 MB: BN-folded W transposed [k][o]
__device__ float g_bstep[DOUT];

// ---------------------------------------------------------------------------
// Inline PTX
// ---------------------------------------------------------------------------
__device__ __forceinline__ uint32_t smem_to_u32(const void* p) {
    uint32_t a;
    asm("{ .reg .u64 t; cvta.to.shared.u64 t, %1; cvt.u32.u64 %0, t; }"
        : "=r"(a) : "l"(p));
    return a;
}

__device__ __forceinline__ void cpasync16(uint32_t s, const void* g) {
    asm volatile("cp.async.cg.shared.global [%0], [%1], 16;"
                 :: "r"(s), "l"(g) : "memory");
}

// Packed dual fp32 FMA: per-half bit-identical to scalar fma.rn.f32.
__device__ __forceinline__ void ffma2(unsigned long long& d,
                                      unsigned long long a,
                                      unsigned long long b) {
    asm("fma.rn.f32x2 %0, %1, %2, %0;" : "+l"(d) : "l"(a), "l"(b));
}

__device__ __forceinline__ unsigned long long pack2(float x) {
    unsigned long long r;
    asm("mov.b64 %0, {%1, %1};" : "=l"(r) : "f"(x));
    return r;
}

__device__ __forceinline__ void unpack2(unsigned long long v, float& lo, float& hi) {
    asm("mov.b64 {%0, %1}, %2;" : "=f"(lo), "=f"(hi) : "l"(v));
}

// ---------------------------------------------------------------------------
// Prep A: transpose A[m][k] -> At[k][m].  128(m) x 32(k) tiles, 256 threads,
// float4 on both gmem sides.
// Load: chunk c in [0,1024): m = c>>3, kq = c&7 -> float4 A[m][4kq..]
//   STS.32 x4 to s[4kq+j][m], pitch 129 (bank = (4kq + j + m)&31 over the
//   warp's (kq 0..7, m 4 vals) -> 32 distinct, conflict-free).
// Store: chunk c: k = c>>5, mq = c&31 -> float4 g_at[k][m0+4mq] from
//   4x LDS.32 (4-way conflict, irrelevant: kernel is DRAM-mix-bound).
// ---------------------------------------------------------------------------
__global__ __launch_bounds__(256)
void transpose_a_kernel(const float* __restrict__ A) {
    __shared__ float s[32][129];
    const int k0 = blockIdx.x * 32;          // 32 k-tiles
    const int m0 = blockIdx.y * 128;         // 256 m-tiles
    const int tid = threadIdx.x;
#pragma unroll
    for (int i = 0; i < 4; i++) {
        const int c = tid + i * 256;
        const int m = c >> 3, kq = c & 7;
        const float4 v = *(const float4*)(A + (size_t)(m0 + m) * DIN + k0 + kq * 4);
        s[kq * 4 + 0][m] = v.x;
        s[kq * 4 + 1][m] = v.y;
        s[kq * 4 + 2][m] = v.z;
        s[kq * 4 + 3][m] = v.w;
    }
    __syncthreads();
#pragma unroll
    for (int i = 0; i < 4; i++) {
        const int c = tid + i * 256;
        const int k = c >> 5, mq = c & 31;
        float4 v;
        v.x = s[k][mq * 4 + 0];
        v.y = s[k][mq * 4 + 1];
        v.z = s[k][mq * 4 + 2];
        v.w = s[k][mq * 4 + 3];
        *(float4*)(g_at + (size_t)(k0 + k) * MTOT + m0 + mq * 4) = v;
    }
}

// ---------------------------------------------------------------------------
// Prep W: fold BN (ratio = gamma/sqrt(var), no eps — same arithmetic as R1)
// and transpose -> Wt[k][o]. Also compute b_step.
// ---------------------------------------------------------------------------
__global__ __launch_bounds__(256)
void prep_w_kernel(const float* __restrict__ w,
                   const float* __restrict__ bias,
                   const float* __restrict__ gamma,
                   const float* __restrict__ beta,
                   const float* __restrict__ mean,
                   const float* __restrict__ var) {
    __shared__ float s[32][33];
    __shared__ float rat[32];
    const int k0 = blockIdx.x * 32;
    const int o0 = blockIdx.y * 32;
    const int tx = threadIdx.x, ty = threadIdx.y;
    if (ty == 0) {
        const int o = o0 + tx;
        const float ratio = gamma[o] / sqrtf(var[o]);
        rat[tx] = ratio;
        if (blockIdx.x == 0) {
            g_bstep[o] = ((bias[o] - mean[o]) * ratio + beta[o]) * (1.0f / (float)TT);
        }
    }
    __syncthreads();
#pragma unroll
    for (int i = 0; i < 4; i++) {
        const int oc = ty + i * 8;
        s[oc][tx] = w[(size_t)(o0 + oc) * DIN + k0 + tx] * rat[oc];
    }
    __syncthreads();
#pragma unroll
    for (int i = 0; i < 4; i++) {
        const int k = ty + i * 8;
        g_wt[(size_t)(k0 + k) * DOUT + o0 + tx] = s[tx][k];
    }
}

// ---------------------------------------------------------------------------
// Stage loader: cp.async straight into [k][row] layout.
// ---------------------------------------------------------------------------
__device__ __forceinline__ void load_stage(uint32_t sbu, int stage, int kt,
                                           int m0, int o0, int tid) {
    const uint32_t st = sbu + stage * STAGE_BYTES;
    const int k0 = kt * KC;
    const float* gA = g_at + (size_t)k0 * MTOT + m0;
    const float* gB = g_wt + (size_t)k0 * DOUT + o0;
#pragma unroll
    for (int i = 0; i < 4; i++) {
        const int c = tid + i * 256;
        const int k = c >> 5, cg = c & 31;
        cpasync16(st + k * 512 + cg * 16, gA + (size_t)k * MTOT + cg * 4);
        cpasync16(st + 16384 + k * 512 + cg * 16, gB + (size_t)k * DOUT + cg * 4);
    }
    asm volatile("cp.async.commit_group;" ::: "memory");
}

// ---------------------------------------------------------------------------
// Fused SGEMM + IF scan, packed-FFMA2, KC=32 fully unrolled, 3-stage.
// Load-before-wait ordering: after the barrier (stage kt-1's readers done),
// issue load(kt+2), THEN wait_group 2 (pending {kt+1, kt+2} allowed; stage kt
// guaranteed complete). Chain: acc=0, k ascending, one fma.rn per k ->
// outputs bit-identical to R1/R5/R6/R8/R9 (rel_err 8.103138e-4).
// ---------------------------------------------------------------------------
__global__ __launch_bounds__(256, 2)
void gemm_if_kernel(float* __restrict__ spike_out,
                    float* __restrict__ count_out) {
    extern __shared__ __align__(16) float smem[];
    const uint32_t sbu = smem_to_u32(smem);

    const int tid  = threadIdx.x;
    const int warp = tid >> 5;
    const int lane = tid & 31;
    const int wr   = warp >> 1;
    const int wc   = warp & 1;
    const int rbase = wr * 32 + ((lane >> 3) << 2);
    const int cbase = wc * 64 + ((lane & 7) << 2);

    const int o0 = blockIdx.x * 128;        // 8 o-tiles (A tiles L2-shared)
    const int m0 = blockIdx.y * 128;        // 256 m-tiles

    unsigned long long acc2[8][4];
#pragma unroll
    for (int i = 0; i < 8; i++)
#pragma unroll
        for (int p = 0; p < 4; p++) acc2[i][p] = 0ull;

    load_stage(sbu, 0, 0, m0, o0, tid);
    load_stage(sbu, 1, 1, m0, o0, tid);

    int stage = 0;
    for (int kt = 0; kt < KTILES; kt++) {
        __syncthreads();                     // stage (kt+2)%3's readers done

        if (kt + 2 < KTILES) {
            int ns = stage + 2; if (ns >= NSTAGE) ns -= NSTAGE;
            load_stage(sbu, ns, kt + 2, m0, o0, tid);
            asm volatile("cp.async.wait_group 2;" ::: "memory");
        } else {
            asm volatile("cp.async.wait_group 0;" ::: "memory");
        }
        __syncthreads();                     // stage kt visible to all threads

        const float* As = smem + stage * STAGE_FLOATS;
        const float* Bs = As + KC * 128;

#pragma unroll
        for (int k = 0; k < KC; k++) {
            float a[8];
            *(float4*)&a[0] = *(const float4*)&As[k * 128 + rbase];
            *(float4*)&a[4] = *(const float4*)&As[k * 128 + rbase + 16];
            const ulonglong2 bv0 = *(const ulonglong2*)&Bs[k * 128 + cbase];
            const ulonglong2 bv1 = *(const ulonglong2*)&Bs[k * 128 + cbase + 32];
#pragma unroll
            for (int i = 0; i < 8; i++) {
                const unsigned long long a2 = pack2(a[i]);
                ffma2(acc2[i][0], a2, bv0.x);
                ffma2(acc2[i][1], a2, bv0.y);
                ffma2(acc2[i][2], a2, bv1.x);
                ffma2(acc2[i][3], a2, bv1.y);
            }
        }

        stage = stage + 1; if (stage >= NSTAGE) stage -= NSTAGE;
    }
    __syncthreads();   // all compute done before reusing smem for staging

    // ---- Epilogue: unpack, stage [o_local][m_local] (pitch 129), IF scan ----
    float* stg = smem;
#pragma unroll
    for (int i = 0; i < 8; i++) {
        const int ml = rbase + (i & 3) + ((i >> 2) << 4);
#pragma unroll
        for (int p = 0; p < 4; p++) {
            float lo, hi;
            unpack2(acc2[i][p], lo, hi);
            const int ol = cbase + ((2 * p) & 3) + ((p >> 1) << 5);
            stg[ol * STG_PITCH + ml]       = lo;
            stg[(ol + 1) * STG_PITCH + ml] = hi;
        }
    }
    __syncthreads();

    // 256 tasks: o_l in [0,128) x n-group {0,1}; m_l = nl*64 + t
    const int ol = tid & 127;
    const int nl = tid >> 7;
    const int n  = (m0 >> 6) + nl;
    const int og = o0 + ol;
    const float bs = g_bstep[og];
    const float* col = stg + ol * STG_PITCH + nl * 64;
    float* so = spike_out + (size_t)n * TT * DOUT + og;

    float pot = 0.0f, cnt = 0.0f;
#pragma unroll 8
    for (int t = 0; t < TT; t++) {
        pot = (pot + col[t]) + bs;          // left-assoc, identical to R1 scan
        const float spk = (pot >= 1.0f) ? 1.0f : 0.0f;
        so[(size_t)t * DOUT] = spk;
        pot -= spk;
        cnt += spk;
    }
    count_out[(size_t)n * DOUT + og] = cnt;
}

// ---------------------------------------------------------------------------
// Launch
// ---------------------------------------------------------------------------
extern "C" void kernel_launch(void* const* d_in, const int* in_sizes, int n_in,
                              void* d_out, int out_size) {
    (void)in_sizes; (void)n_in; (void)out_size;

    const float* x_st  = (const float*)d_in[0];  // (512, 64, 1024) binary
    const float* w     = (const float*)d_in[2];
    const float* bias  = (const float*)d_in[3];
    const float* gamma = (const float*)d_in[4];
    const float* beta  = (const float*)d_in[5];
    const float* mean  = (const float*)d_in[6];
    const float* var   = (const float*)d_in[7];

    float* out       = (float*)d_out;
    float* spike_out = out;                                 // 512*64*1024
    float* count_out = out + (size_t)MTOT * DOUT;           // 512*1024

    {
        dim3 grdA(DIN / 32, MTOT / 128);                    // (32, 256)
        transpose_a_kernel<<<grdA, 256>>>(x_st);
        dim3 blk(32, 8);
        dim3 grd2(DIN / 32, DOUT / 32);                     // (32, 32)
        prep_w_kernel<<<grd2, blk>>>(w, bias, gamma, beta, mean, var);
    }

    cudaFuncSetAttribute(gemm_if_kernel,
                         cudaFuncAttributeMaxDynamicSharedMemorySize, SMEM_BYTES);

    dim3 grid(DOUT / 128, MTOT / 128);                      // (8, 256)
    gemm_if_kernel<<<grid, 256, SMEM_BYTES>>>(spike_out, count_out);
}